// round 12
// baseline (speedup 1.0000x reference)
#include <cuda_runtime.h>
#include <cuda_fp16.h>
#include <math.h>
#include <stdint.h>

// ---------------------------------------------------------------------------
// Dims: D=512, K=8, L=64, Q=4096, C=4096.  All GEMMs on fp16 m16n8k16 mma
// (fp16 mantissa == tf32 mantissa; power-of-2 scaling keeps rounding identical
// to the validated tf32 scheme).
//   T (B-pack fp16, x2^8)  = class @ M        (3-MMA hi/lo split, ~2^-22)
//   other[q,c] = b + sum_k w_k*relu(q.Tk)     (1 MMA/k16)
//   sc  = softmax_rows(other)                 (A-pack fp16, x2^6)
//   qfp[z] = sc @ class                       (1 MMA/k16, split-K=8)
//   out = tanh((query + sum_z qfp) @ hash_w^T + b)   (fused SIMT)
// Target sm_103 (no 'a'): mma.sync/cp.async only.
// All mma kernels: 512 threads, warp grid 4x4, warp tile 32x32.
// ---------------------------------------------------------------------------

__device__ __half g_T16[(size_t)8 * 4096 * 512];   // T, B-pack, x2^8 (32MB)
__device__ float  g_other[(size_t)4096 * 4096];    // logits fp32 (64MB)
__device__ __half g_sc16[(size_t)4096 * 4096];     // scores A-pack x2^6 (32MB)
__device__ __half g_q16[(size_t)4096 * 512];       // query A-pack x2^8
__device__ __half g_cah[(size_t)4096 * 512];       // class A-pack hi (x2^8)
__device__ __half g_cal[(size_t)4096 * 512];       // class A-pack lo
__device__ __half g_mbh[(size_t)4096 * 512];       // M^T B-pack hi (x2^10)
__device__ __half g_mbl[(size_t)4096 * 512];       // M^T B-pack lo
__device__ __half g_cbh[(size_t)512 * 4096];       // class^T B-pack (x2^8)
__device__ float  g_qfp[(size_t)8 * 4096 * 512];   // split-K partials (64MB)
__device__ float  g_hwT[512 * 64];

// ------------------------------ helpers -----------------------------------
__device__ __forceinline__ uint32_t smem_u32(const void* p) {
    uint32_t a;
    asm("{ .reg .u64 t; cvta.to.shared.u64 t, %1; cvt.u32.u64 %0, t; }" : "=r"(a) : "l"(p));
    return a;
}
__device__ __forceinline__ void mma_f16(float* c, const uint32_t* a, const uint32_t* b) {
    asm volatile(
        "mma.sync.aligned.m16n8k16.row.col.f32.f16.f16.f32 "
        "{%0,%1,%2,%3}, {%4,%5,%6,%7}, {%8,%9}, {%0,%1,%2,%3};"
        : "+f"(c[0]), "+f"(c[1]), "+f"(c[2]), "+f"(c[3])
        : "r"(a[0]), "r"(a[1]), "r"(a[2]), "r"(a[3]), "r"(b[0]), "r"(b[1]));
}
// packed offsets (64-k chunk granularity), element (m|n, k), reduction Ktot
__device__ __forceinline__ size_t apack16(int m, int k, int Ktot) {
    return ((size_t)(m >> 7) * (Ktot >> 6) + (k >> 6)) * 8192
         + (size_t)(((((m >> 4) & 7) << 2) + ((k >> 4) & 3)) * 256
         + (((m & 7) << 2) + ((k & 7) >> 1)) * 8
         + (((k >> 3) & 1) << 2) + (((m >> 3) & 1) << 1) + (k & 1));
}
__device__ __forceinline__ size_t bpack16(int n, int k, int Ktot) {
    return ((size_t)(n >> 7) * (Ktot >> 6) + (k >> 6)) * 8192
         + (size_t)(((((n >> 3) & 15) << 2) + ((k >> 4) & 3)) * 128
         + (((n & 7) << 2) + ((k & 7) >> 1)) * 4
         + (((k >> 3) & 1) << 1) + (k & 1));
}

// ---------------------------------------------------------------------------
// fp16 mma GEMM (stages 1 & 4): out = A @ B^T, operands fragment-packed.
//   SPLIT=1: A,B hi/lo (3 MMA/k16, ~2^-22)   SPLIT=0: single (1 MMA/k16)
//   EPI 0: scatter fp16(acc*2^-10) to T16 B-pack (Ktot_out=512)
//   EPI 1: store fp32 acc*2^-14 partial to out + z*4096*512
// CTA 128m x 128n, 512 threads (4x4 warps, 32x32 warp tile), 64-k chunks,
// 3-stage cp.async pipeline.
// ---------------------------------------------------------------------------
template <int SPLIT, int EPI>
__global__ void __launch_bounds__(512, 1)
gemm_f16(const __half* __restrict__ Ah, const __half* __restrict__ Al,
         const __half* __restrict__ Bh, const __half* __restrict__ Bl,
         float* __restrict__ out, __half* __restrict__ outh,
         int Ktot, int kseg)
{
    extern __shared__ char smc[];
    __half* sm = (__half*)smc;
    constexpr int SF = (SPLIT ? 4 : 2) * 8192;   // halves per stage

    const int tid = threadIdx.x;
    const int lane = tid & 31;
    const int wid = tid >> 5;          // 0..15
    const int wm = wid >> 2;           // 0..3
    const int wn = wid & 3;            // 0..3
    const int m0 = blockIdx.y * 128;
    const int n0 = blockIdx.x * 128;
    const int kstart = blockIdx.z * kseg;
    const int nchunks = kseg / 64;

    const size_t aBlk = ((size_t)(m0 >> 7) * (Ktot >> 6) + (kstart >> 6)) * 8192;
    const size_t bBlk = ((size_t)(n0 >> 7) * (Ktot >> 6) + (kstart >> 6)) * 8192;

    float macc[2][4][4];
#pragma unroll
    for (int mi = 0; mi < 2; mi++)
#pragma unroll
        for (int ni = 0; ni < 4; ni++)
#pragma unroll
            for (int r = 0; r < 4; r++) macc[mi][ni][r] = 0.0f;

    auto issue = [&](int it, int s) {
        const size_t cofs = (size_t)it * 8192 + tid * 8;
        uint32_t base = smem_u32(sm + s * SF) + tid * 16;
        // Ah (16KB): 2 passes of 8KB
#pragma unroll
        for (int p = 0; p < 2; p++)
            asm volatile("cp.async.cg.shared.global [%0], [%1], 16;"
                         :: "r"(base + p * 8192), "l"(Ah + aBlk + cofs + p * 4096));
        if (SPLIT) {
#pragma unroll
            for (int p = 0; p < 2; p++)
                asm volatile("cp.async.cg.shared.global [%0], [%1], 16;"
                             :: "r"(base + 16384 + p * 8192), "l"(Al + aBlk + cofs + p * 4096));
        }
        uint32_t bb = base + (SPLIT ? 32768 : 16384);
#pragma unroll
        for (int p = 0; p < 2; p++)
            asm volatile("cp.async.cg.shared.global [%0], [%1], 16;"
                         :: "r"(bb + p * 8192), "l"(Bh + bBlk + cofs + p * 4096));
        if (SPLIT) {
#pragma unroll
            for (int p = 0; p < 2; p++)
                asm volatile("cp.async.cg.shared.global [%0], [%1], 16;"
                             :: "r"(bb + 16384 + p * 8192), "l"(Bl + bBlk + cofs + p * 4096));
        }
        asm volatile("cp.async.commit_group;" ::: "memory");
    };

    issue(0, 0);
    issue(1, 1);

    int s = 0;
#pragma unroll 1
    for (int it = 0; it < nchunks; it++) {
        if (it < nchunks - 1) asm volatile("cp.async.wait_group 1;" ::: "memory");
        else                  asm volatile("cp.async.wait_group 0;" ::: "memory");
        __syncthreads();
        if (it + 2 < nchunks) {
            int s2 = s + 2; if (s2 >= 3) s2 -= 3;
            issue(it + 2, s2);
        }

        const __half* pa  = sm + s * SF;
        const __half* pal = pa + 8192;
        const __half* pbh = pa + (SPLIT ? 16384 : 8192);
        const __half* pbl = pbh + 8192;
#pragma unroll
        for (int kk = 0; kk < 4; kk++) {
            uint4 ah[2], al[2];
            uint2 bh[4], bl[4];
#pragma unroll
            for (int mi = 0; mi < 2; mi++) {
                int ao = (((wm * 2 + mi) * 4 + kk) << 8) + lane * 8;
                ah[mi] = *(const uint4*)(pa + ao);
                if (SPLIT) al[mi] = *(const uint4*)(pal + ao);
            }
#pragma unroll
            for (int ni = 0; ni < 4; ni++) {
                int bo = (((wn * 4 + ni) * 4 + kk) << 7) + lane * 4;
                bh[ni] = *(const uint2*)(pbh + bo);
                if (SPLIT) bl[ni] = *(const uint2*)(pbl + bo);
            }
            // pass 1: hi*hi (8 independent chains)
#pragma unroll
            for (int mi = 0; mi < 2; mi++)
#pragma unroll
                for (int ni = 0; ni < 4; ni++)
                    mma_f16(macc[mi][ni], (const uint32_t*)&ah[mi], (const uint32_t*)&bh[ni]);
            if (SPLIT) {
                // pass 2: lo*hi
#pragma unroll
                for (int mi = 0; mi < 2; mi++)
#pragma unroll
                    for (int ni = 0; ni < 4; ni++)
                        mma_f16(macc[mi][ni], (const uint32_t*)&al[mi], (const uint32_t*)&bh[ni]);
                // pass 3: hi*lo
#pragma unroll
                for (int mi = 0; mi < 2; mi++)
#pragma unroll
                    for (int ni = 0; ni < 4; ni++)
                        mma_f16(macc[mi][ni], (const uint32_t*)&ah[mi], (const uint32_t*)&bl[ni]);
            }
        }
        if (++s >= 3) s -= 3;
    }

    const int lq = lane >> 2;
    const int ld = lane & 3;
    if (EPI == 0) {
        // scale: A x2^8 * B x2^10 = acc x2^18; want T x2^8 -> *2^-10
        const float ds = 0.0009765625f;
#pragma unroll
        for (int mi = 0; mi < 2; mi++) {
            const int r = m0 + wm * 32 + mi * 16 + lq;
#pragma unroll
            for (int ni = 0; ni < 4; ni++) {
                const int c = n0 + wn * 32 + ni * 8 + 2 * ld;
#pragma unroll
                for (int rr = 0; rr < 4; rr++) {
                    int row = r + (rr >> 1) * 8;
                    int col = c + (rr & 1);
                    int kp = col & 7, dd = col >> 3;
                    outh[(size_t)kp * 2097152 + bpack16(row, dd, 512)] =
                        __float2half_rn(macc[mi][ni][rr] * ds);
                }
            }
        }
    } else {
        // scale: sc x2^6 * class x2^8 = acc x2^14 -> *2^-14
        const float ds = 6.103515625e-05f;
        float* ob = out + (size_t)blockIdx.z * 4096 * 512;
#pragma unroll
        for (int mi = 0; mi < 2; mi++) {
            const int r = m0 + wm * 32 + mi * 16 + lq;
#pragma unroll
            for (int ni = 0; ni < 4; ni++) {
                const int c = n0 + wn * 32 + ni * 8 + 2 * ld;
                *(float2*)(ob + (size_t)r * 512 + c) =
                    make_float2(macc[mi][ni][0] * ds, macc[mi][ni][1] * ds);
                *(float2*)(ob + (size_t)(r + 8) * 512 + c) =
                    make_float2(macc[mi][ni][2] * ds, macc[mi][ni][3] * ds);
            }
        }
    }
}

// ---------------------------------------------------------------------------
// Stage 2: fused bilinear + relu + score, fp16 single x single (1 MMA/k16).
// CTA 128q x 128c, 512 threads; 128-d chunks; 3-stage pipeline (192KB).
// ---------------------------------------------------------------------------
#define S2_SF 32768                       // halves per stage (A 16K + B 16K)
#define S2_SMEM (3 * S2_SF * 2)           // 196608 B

__global__ void __launch_bounds__(512, 1)
stage2_f16(const __half* __restrict__ q16, const __half* __restrict__ T16,
           const float* __restrict__ score_w, const float* __restrict__ score_b,
           float* __restrict__ other)
{
    extern __shared__ char smc[];
    __half* sm = (__half*)smc;
    const int tid = threadIdx.x;
    const int lane = tid & 31;
    const int wid = tid >> 5;
    const int wm = wid >> 2;
    const int wn = wid & 3;
    const int q0 = blockIdx.y * 128;
    const int c0 = blockIdx.x * 128;

    const size_t aBase = (size_t)(q0 >> 7) * 8 * 8192;
    const size_t bBase = (size_t)(c0 >> 7) * 8 * 8192;

    float sacc[2][4][4];
#pragma unroll
    for (int mi = 0; mi < 2; mi++)
#pragma unroll
        for (int ni = 0; ni < 4; ni++)
#pragma unroll
            for (int r = 0; r < 4; r++) sacc[mi][ni][r] = 0.0f;

    // it = k*4 + t (t: 128-d chunk within slab)
    auto issue = [&](int it, int s) {
        const int k = it >> 2, t = it & 3;
        const __half* srcA = q16 + aBase + (size_t)t * 16384 + tid * 8;
        const __half* srcB = T16 + (size_t)k * 2097152 + bBase + (size_t)t * 16384 + tid * 8;
        uint32_t da = smem_u32(sm + s * S2_SF) + tid * 16;
        uint32_t db = da + 32768;
#pragma unroll
        for (int p = 0; p < 4; p++) {
            asm volatile("cp.async.cg.shared.global [%0], [%1], 16;"
                         :: "r"(da + p * 8192), "l"(srcA + p * 4096));
            asm volatile("cp.async.cg.shared.global [%0], [%1], 16;"
                         :: "r"(db + p * 8192), "l"(srcB + p * 4096));
        }
        asm volatile("cp.async.commit_group;" ::: "memory");
    };

    issue(0, 0);
    issue(1, 1);

    float macc[2][4][4];
    int s = 0;
#pragma unroll 1
    for (int it = 0; it < 32; it++) {
        const int k = it >> 2, t = it & 3;
        if (t == 0) {
#pragma unroll
            for (int mi = 0; mi < 2; mi++)
#pragma unroll
                for (int ni = 0; ni < 4; ni++)
#pragma unroll
                    for (int r = 0; r < 4; r++) macc[mi][ni][r] = 0.0f;
        }

        if (it < 31) asm volatile("cp.async.wait_group 1;" ::: "memory");
        else         asm volatile("cp.async.wait_group 0;" ::: "memory");
        __syncthreads();
        if (it + 2 < 32) {
            int s2 = s + 2; if (s2 >= 3) s2 -= 3;
            issue(it + 2, s2);
        }

        const __half* pa = sm + s * S2_SF;
        const __half* pb = pa + 16384;
#pragma unroll
        for (int kk = 0; kk < 8; kk++) {
            const int sub = (kk >> 2) * 8192;
            const int kf = kk & 3;
            uint4 a[2];
            uint2 b[4];
#pragma unroll
            for (int mi = 0; mi < 2; mi++)
                a[mi] = *(const uint4*)(pa + sub + (((wm * 2 + mi) * 4 + kf) << 8) + lane * 8);
#pragma unroll
            for (int ni = 0; ni < 4; ni++)
                b[ni] = *(const uint2*)(pb + sub + (((wn * 4 + ni) * 4 + kf) << 7) + lane * 4);
#pragma unroll
            for (int mi = 0; mi < 2; mi++)
#pragma unroll
                for (int ni = 0; ni < 4; ni++)
                    mma_f16(macc[mi][ni], (const uint32_t*)&a[mi], (const uint32_t*)&b[ni]);
        }

        if (t == 3) {
            // acc = P * 2^16 (q x2^8, T x2^8): fold 2^-16 into w
            const float w = __ldg(score_w + k) * 1.52587890625e-05f;
#pragma unroll
            for (int mi = 0; mi < 2; mi++)
#pragma unroll
                for (int ni = 0; ni < 4; ni++)
#pragma unroll
                    for (int r = 0; r < 4; r++)
                        sacc[mi][ni][r] = fmaf(fmaxf(macc[mi][ni][r], 0.0f), w,
                                               sacc[mi][ni][r]);
        }
        if (++s >= 3) s -= 3;
    }

    const int lq = lane >> 2;
    const int ld = lane & 3;
    const float sb = __ldg(score_b);
#pragma unroll
    for (int mi = 0; mi < 2; mi++) {
        const int q = q0 + wm * 32 + mi * 16 + lq;
#pragma unroll
        for (int ni = 0; ni < 4; ni++) {
            const int c = c0 + wn * 32 + ni * 8 + 2 * ld;
            *(float2*)(other + (size_t)q * 4096 + c) =
                make_float2(sb + sacc[mi][ni][0], sb + sacc[mi][ni][1]);
            *(float2*)(other + (size_t)(q + 8) * 4096 + c) =
                make_float2(sb + sacc[mi][ni][2], sb + sacc[mi][ni][3]);
        }
    }
}

// ---------------------------------------------------------------------------
// Softmax (paired rows q, q+8); fp16 A-pack output (Ktot=4096, x2^6).
// Thread handles 16 consecutive columns -> one contiguous 64B packed block.
// ---------------------------------------------------------------------------
__global__ void softmax_pack2(const float* __restrict__ o, __half* __restrict__ sc)
{
    const int b = blockIdx.x;
    const int qa = ((b >> 3) << 4) | (b & 7);
    const int tid = threadIdx.x;

    float v0[16], v1[16];
    {
        const float4* p0 = (const float4*)(o + (size_t)qa * 4096) + tid * 4;
        const float4* p1 = (const float4*)(o + (size_t)(qa + 8) * 4096) + tid * 4;
#pragma unroll
        for (int i = 0; i < 4; i++) {
            float4 x = p0[i];
            v0[i * 4] = x.x; v0[i * 4 + 1] = x.y; v0[i * 4 + 2] = x.z; v0[i * 4 + 3] = x.w;
            float4 y = p1[i];
            v1[i * 4] = y.x; v1[i * 4 + 1] = y.y; v1[i * 4 + 2] = y.z; v1[i * 4 + 3] = y.w;
        }
    }
    float mx0 = -1e30f, mx1 = -1e30f;
#pragma unroll
    for (int i = 0; i < 16; i++) { mx0 = fmaxf(mx0, v0[i]); mx1 = fmaxf(mx1, v1[i]); }

    __shared__ float sm0[8], sm1[8];
#pragma unroll
    for (int o2 = 16; o2 > 0; o2 >>= 1) {
        mx0 = fmaxf(mx0, __shfl_xor_sync(0xffffffffu, mx0, o2));
        mx1 = fmaxf(mx1, __shfl_xor_sync(0xffffffffu, mx1, o2));
    }
    if ((tid & 31) == 0) { sm0[tid >> 5] = mx0; sm1[tid >> 5] = mx1; }
    __syncthreads();
    mx0 = sm0[0]; mx1 = sm1[0];
#pragma unroll
    for (int i = 1; i < 8; i++) { mx0 = fmaxf(mx0, sm0[i]); mx1 = fmaxf(mx1, sm1[i]); }
    __syncthreads();

    float s0 = 0.0f, s1 = 0.0f;
#pragma unroll
    for (int i = 0; i < 16; i++) {
        v0[i] = expf(v0[i] - mx0); s0 += v0[i];
        v1[i] = expf(v1[i] - mx1); s1 += v1[i];
    }
#pragma unroll
    for (int o2 = 16; o2 > 0; o2 >>= 1) {
        s0 += __shfl_xor_sync(0xffffffffu, s0, o2);
        s1 += __shfl_xor_sync(0xffffffffu, s1, o2);
    }
    if ((tid & 31) == 0) { sm0[tid >> 5] = s0; sm1[tid >> 5] = s1; }
    __syncthreads();
    s0 = 0.0f; s1 = 0.0f;
#pragma unroll
    for (int i = 0; i < 8; i++) { s0 += sm0[i]; s1 += sm1[i]; }
    const float i0 = 64.0f / s0, i1 = 64.0f / s1;   // fold x2^6 scale

    // pack: 32 halves (rows qa, qa+8 x 16 k) = one 64B contiguous block
    __half hbuf[32];
#pragma unroll
    for (int j = 0; j < 32; j++) {
        int t2 = j >> 3, kb3 = (j >> 2) & 1, mrow = (j >> 1) & 1, h = j & 1;
        int kl = kb3 * 8 + t2 * 2 + h;
        hbuf[j] = __float2half_rn(mrow ? v1[kl] * i1 : v0[kl] * i0);
    }
    __half* dst = sc + apack16(qa, tid * 16, 4096);
#pragma unroll
    for (int j = 0; j < 4; j++)
        *(uint4*)(dst + j * 8) = *(const uint4*)(hbuf + j * 8);
}

// ---------------------------------------------------------------------------
// Fused stage 5: qf = query + sum_z qfp[z] (smem), out = tanh(qf @ hwT + b).
// ---------------------------------------------------------------------------
__global__ void __launch_bounds__(256, 2)
stage5_fused(const float* __restrict__ query, const float* __restrict__ qfp,
             const float* __restrict__ hwT, const float* __restrict__ hash_b,
             float* __restrict__ out)
{
    __shared__ float qf_s[16 * 512];
    const int tid = threadIdx.x;
    const int qbase = blockIdx.x * 16;
    const size_t S = (size_t)4096 * 512;
    const size_t gbase = (size_t)qbase * 512;

#pragma unroll
    for (int j = 0; j < 8; j++) {
        int i4 = tid + j * 256;
        size_t g = gbase + (size_t)i4 * 4;
        float4 acc = *(const float4*)(query + g);
#pragma unroll
        for (int z = 0; z < 8; z++) {
            float4 p = *(const float4*)(qfp + z * S + g);
            acc.x += p.x; acc.y += p.y; acc.z += p.z; acc.w += p.w;
        }
        *(float4*)(qf_s + i4 * 4) = acc;
    }
    __syncthreads();

    const int q = tid >> 4;
    const int lb = (tid & 15) * 4;
    float a0 = 0, a1 = 0, a2 = 0, a3 = 0;
    const float* qr = qf_s + q * 512;
#pragma unroll 4
    for (int d = 0; d < 512; d += 4) {
        float4 qv = *(const float4*)(qr + d);
        float4 h0 = __ldg((const float4*)(hwT + (size_t)d * 64 + lb));
        float4 h1 = __ldg((const float4*)(hwT + (size_t)(d + 1) * 64 + lb));
        float4 h2 = __ldg((const float4*)(hwT + (size_t)(d + 2) * 64 + lb));
        float4 h3 = __ldg((const float4*)(hwT + (size_t)(d + 3) * 64 + lb));
        a0 = fmaf(qv.x, h0.x, fmaf(qv.y, h1.x, fmaf(qv.z, h2.x, fmaf(qv.w, h3.x, a0))));
        a1 = fmaf(qv.x, h0.y, fmaf(qv.y, h1.y, fmaf(qv.z, h2.y, fmaf(qv.w, h3.y, a1))));
        a2 = fmaf(qv.x, h0.z, fmaf(qv.y, h1.z, fmaf(qv.z, h2.z, fmaf(qv.w, h3.z, a2))));
        a3 = fmaf(qv.x, h0.w, fmaf(qv.y, h1.w, fmaf(qv.z, h2.w, fmaf(qv.w, h3.w, a3))));
    }
    float4 hb = __ldg((const float4*)(hash_b + lb));
    float4 r = make_float4(tanhf(a0 + hb.x), tanhf(a1 + hb.y),
                           tanhf(a2 + hb.z), tanhf(a3 + hb.w));
    *(float4*)(out + (size_t)(qbase + q) * 64 + lb) = r;
}

// ---------------------------------------------------------------------------
// Prep kernels
// ---------------------------------------------------------------------------
__global__ void transpose_hw(const float* __restrict__ hw)
{
    int idx = blockIdx.x * blockDim.x + threadIdx.x;
    int l = idx >> 9;
    int d = idx & 511;
    g_hwT[d * 64 + l] = hw[idx];
}

// query -> A-pack fp16 x2^8. Thread handles rows (m, m+8) x 16 k -> 64B store.
__global__ void pack_q16(const float* __restrict__ q)
{
    int t = blockIdx.x * blockDim.x + threadIdx.x;   // 65536
    int kg = t & 31;
    int pr = t >> 5;                                  // 0..2047
    int m0 = ((pr >> 3) << 4) | (pr & 7);
    int kb = kg * 16;

    float v0[16], v1[16];
    const float4* p0 = (const float4*)(q + (size_t)m0 * 512 + kb);
    const float4* p1 = (const float4*)(q + (size_t)(m0 + 8) * 512 + kb);
#pragma unroll
    for (int i = 0; i < 4; i++) {
        float4 x = p0[i];
        v0[i*4] = x.x; v0[i*4+1] = x.y; v0[i*4+2] = x.z; v0[i*4+3] = x.w;
        float4 y = p1[i];
        v1[i*4] = y.x; v1[i*4+1] = y.y; v1[i*4+2] = y.z; v1[i*4+3] = y.w;
    }
    __half hbuf[32];
#pragma unroll
    for (int j = 0; j < 32; j++) {
        int t2 = j >> 3, kb3 = (j >> 2) & 1, mrow = (j >> 1) & 1, h = j & 1;
        int kl = kb3 * 8 + t2 * 2 + h;
        hbuf[j] = __float2half_rn((mrow ? v1[kl] : v0[kl]) * 256.0f);
    }
    __half* dst = g_q16 + apack16(m0, kb, 512);
#pragma unroll
    for (int j = 0; j < 4; j++)
        *(uint4*)(dst + j * 8) = *(const uint4*)(hbuf + j * 8);
}

// class -> A-pack fp16 hi/lo x2^8 (same structure)
__global__ void pack_classA16(const float* __restrict__ cv)
{
    int t = blockIdx.x * blockDim.x + threadIdx.x;
    int kg = t & 31;
    int pr = t >> 5;
    int m0 = ((pr >> 3) << 4) | (pr & 7);
    int kb = kg * 16;

    float v0[16], v1[16];
    const float4* p0 = (const float4*)(cv + (size_t)m0 * 512 + kb);
    const float4* p1 = (const float4*)(cv + (size_t)(m0 + 8) * 512 + kb);
#pragma unroll
    for (int i = 0; i < 4; i++) {
        float4 x = p0[i];
        v0[i*4] = x.x; v0[i*4+1] = x.y; v0[i*4+2] = x.z; v0[i*4+3] = x.w;
        float4 y = p1[i];
        v1[i*4] = y.x; v1[i*4+1] = y.y; v1[i*4+2] = y.z; v1[i*4+3] = y.w;
    }
    __half hb[32], lb[32];
#pragma unroll
    for (int j = 0; j < 32; j++) {
        int t2 = j >> 3, kb3 = (j >> 2) & 1, mrow = (j >> 1) & 1, h = j & 1;
        int kl = kb3 * 8 + t2 * 2 + h;
        float v = (mrow ? v1[kl] : v0[kl]) * 256.0f;
        __half hi = __float2half_rn(v);
        hb[j] = hi;
        lb[j] = __float2half_rn(v - __half2float(hi));
    }
    size_t off = apack16(m0, kb, 512);
#pragma unroll
    for (int j = 0; j < 4; j++) {
        *(uint4*)(g_cah + off + j * 8) = *(const uint4*)(hb + j * 8);
        *(uint4*)(g_cal + off + j * 8) = *(const uint4*)(lb + j * 8);
    }
}

// in [R][C] (R=k-dim, C=n-dim) -> B-pack fp16 hi/lo, one thread per 16-k group.
__global__ void pack_B16_split(const float* __restrict__ in,
                               __half* __restrict__ ohi, __half* __restrict__ olo,
                               int R, int C, float scale)
{
    unsigned tt = blockIdx.x * blockDim.x + threadIdx.x;
    unsigned k16 = tt / (unsigned)C;
    unsigned n = tt - k16 * (unsigned)C;
    int kb = (int)k16 * 16;

    unsigned short h[16], l[16];
#pragma unroll
    for (int i = 0; i < 16; i++) {
        float v = in[(size_t)(kb + i) * C + n] * scale;
        __half hv = __float2half_rn(v);
        h[i] = __half_as_ushort(hv);
        l[i] = __half_as_ushort(__float2half_rn(v - __half2float(hv)));
    }
    size_t base = bpack16((int)n, kb, R);
    const int map[16] = {0,1,8,9,2,3,10,11,4,5,12,13,6,7,14,15};
    uint32_t uh[8], ul[8];
#pragma unroll
    for (int j = 0; j < 8; j++) {
        uh[j] = (uint32_t)h[map[2*j]] | ((uint32_t)h[map[2*j+1]] << 16);
        ul[j] = (uint32_t)l[map[2*j]] | ((uint32_t)l[map[2*j+1]] << 16);
    }
    *(uint4*)(ohi + base)     = make_uint4(uh[0], uh[1], uh[2], uh[3]);
    *(uint4*)(ohi + base + 8) = make_uint4(uh[4], uh[5], uh[6], uh[7]);
    *(uint4*)(olo + base)     = make_uint4(ul[0], ul[1], ul[2], ul[3]);
    *(uint4*)(olo + base + 8) = make_uint4(ul[4], ul[5], ul[6], ul[7]);
}

// class^T -> B-pack fp16 single x2^8 (N=512 d-dim, K=4096 c-dim)
__global__ void pack_classB16(const float* __restrict__ cv)
{
    unsigned tt = blockIdx.x * blockDim.x + threadIdx.x;
    unsigned c16 = tt / 512u;
    unsigned d = tt - c16 * 512u;
    int cb = (int)c16 * 16;

    unsigned short h[16];
#pragma unroll
    for (int i = 0; i < 16; i++)
        h[i] = __half_as_ushort(__float2half_rn(cv[(size_t)(cb + i) * 512 + d] * 256.0f));
    size_t base = bpack16((int)d, cb, 4096);
    const int map[16] = {0,1,8,9,2,3,10,11,4,5,12,13,6,7,14,15};
    uint32_t u[8];
#pragma unroll
    for (int j = 0; j < 8; j++)
        u[j] = (uint32_t)h[map[2*j]] | ((uint32_t)h[map[2*j+1]] << 16);
    *(uint4*)(g_cbh + base)     = make_uint4(u[0], u[1], u[2], u[3]);
    *(uint4*)(g_cbh + base + 8) = make_uint4(u[4], u[5], u[6], u[7]);
}

// ---------------------------------------------------------------------------
extern "C" void kernel_launch(void* const* d_in, const int* in_sizes, int n_in,
                              void* d_out, int out_size)
{
    const float* class_v = (const float*)d_in[0];
    const float* query_v = (const float*)d_in[1];
    const float* Mmat    = (const float*)d_in[2];
    const float* score_w = (const float*)d_in[3];
    const float* score_b = (const float*)d_in[4];
    const float* hash_w  = (const float*)d_in[5];
    const float* hash_b  = (const float*)d_in[6];
    float* out = (float*)d_out;

    float *other, *qfp, *hwT;
    __half *T16, *sc16, *q16, *cah, *cal, *mbh, *mbl, *cbh;
    cudaGetSymbolAddress((void**)&T16, g_T16);
    cudaGetSymbolAddress((void**)&other, g_other);
    cudaGetSymbolAddress((void**)&sc16, g_sc16);
    cudaGetSymbolAddress((void**)&q16, g_q16);
    cudaGetSymbolAddress((void**)&cah, g_cah);
    cudaGetSymbolAddress((void**)&cal, g_cal);
    cudaGetSymbolAddress((void**)&mbh, g_mbh);
    cudaGetSymbolAddress((void**)&mbl, g_mbl);
    cudaGetSymbolAddress((void**)&cbh, g_cbh);
    cudaGetSymbolAddress((void**)&qfp, g_qfp);
    cudaGetSymbolAddress((void**)&hwT, g_hwT);

    cudaFuncSetAttribute(stage2_f16, cudaFuncAttributeMaxDynamicSharedMemorySize, S2_SMEM);
    cudaFuncSetAttribute(gemm_f16<1, 0>, cudaFuncAttributeMaxDynamicSharedMemorySize,
                         3 * 4 * 8192 * 2);
    cudaFuncSetAttribute(gemm_f16<0, 1>, cudaFuncAttributeMaxDynamicSharedMemorySize,
                         3 * 2 * 8192 * 2);

    // prep
    pack_q16<<<256, 256>>>(query_v);
    pack_classA16<<<256, 256>>>(class_v);
    pack_B16_split<<<512, 256>>>(Mmat, mbh, mbl, 512, 4096, 1024.0f);  // M x2^10

    // Stage 1: T = class @ M  (fp16 3-MMA split, scatter to B-pack)
    gemm_f16<1, 0><<<dim3(32, 32, 1), 512, 3 * 4 * 8192 * 2>>>(
        cah, cal, mbh, mbl, nullptr, T16, 512, 512);

    pack_classB16<<<512, 256>>>(class_v);

    // Stage 2: fused bilinear + relu + score (fp16, 1 MMA/k16)
    stage2_f16<<<dim3(32, 32), 512, S2_SMEM>>>(q16, T16, score_w, score_b, other);

    // Stage 3: softmax -> fp16 packed scores
    softmax_pack2<<<2048, 256>>>(other, sc16);

    // Stage 4: qf partials = sc @ class (fp16 single, split-K=8)
    gemm_f16<0, 1><<<dim3(4, 32, 8), 512, 3 * 2 * 8192 * 2>>>(
        sc16, nullptr, cbh, nullptr, qfp, nullptr, 4096, 512);

    transpose_hw<<<128, 256>>>(hash_w);

    // Stage 5 (fused reduce + residual + tanh GEMM)
    stage5_fused<<<256, 256>>>(query_v, qfp, hwT, hash_b, out);
}